// round 1
// baseline (speedup 1.0000x reference)
#include <cuda_runtime.h>
#include <math.h>

// Problem shape (fixed by reference): B=32, N=4096, D=256, H=256
#define BB 32
#define NN 4096
#define DD 256
#define HH 256
#define MTOT (BB * NN)   // 131072 rows

#define TM 64            // rows per block in scores kernel
#define KC 16            // d-chunk size
#define NCHUNK 16        // N chunks in weighted-sum kernel (4096/256)

// ---------------- device scratch (no allocation allowed) ----------------
__device__ float g_scores[MTOT];                 // 512 KB
__device__ float g_bmax[BB];
__device__ float g_bden[BB];
__device__ float g_part[BB][NCHUNK][DD];         // 512 KB partial weighted sums

// ---------------- packed f32x2 helpers (Blackwell) ----------------
__device__ __forceinline__ void fma2(unsigned long long& acc,
                                     unsigned long long a,
                                     unsigned long long b) {
    asm("fma.rn.f32x2 %0, %1, %2, %0;" : "+l"(acc) : "l"(a), "l"(b));
}
__device__ __forceinline__ unsigned long long bcast2(float x) {
    unsigned long long r;
    unsigned int u = __float_as_uint(x);
    asm("mov.b64 %0, {%1, %1};" : "=l"(r) : "r"(u));
    return r;
}
__device__ __forceinline__ void unpack2(unsigned long long p, float& lo, float& hi) {
    unsigned int a, b;
    asm("mov.b64 {%0, %1}, %2;" : "=r"(a), "=r"(b) : "l"(p));
    lo = __uint_as_float(a);
    hi = __uint_as_float(b);
}

// =====================================================================
// Kernel A: scores[m] = sum_h Wv[h] * tanh( sum_d Wq[h,d]*Q[m,d] + Wk[h,d]*K[m,d] )
//
// Block: 256 threads = 16(tx) x 16(ty). Block tile: 64 rows x all 256 h.
// Thread tile: 4 rows (ty*4..+3) x 16 h. The 16 h per thread are the 8 pairs
// { tx*2 + 32*j, tx*2 + 32*j + 1 : j=0..7 } — stride-32 pair assignment makes
// every W shared-memory read a fully coalesced, conflict-free LDS.64, and the
// h-order is irrelevant because h is immediately reduced against Wv.
// Accumulators are f32x2 packs -> fma.rn.f32x2 doubles fp32 FMA throughput.
// =====================================================================
__global__ __launch_bounds__(256) void scores_kernel(
    const float* __restrict__ Q, const float* __restrict__ K,
    const float* __restrict__ Wq, const float* __restrict__ Wk,
    const float* __restrict__ Wv)
{
    __shared__ float Xq[KC][TM + 4];       // d-major, transposed
    __shared__ float Xk[KC][TM + 4];
    __shared__ float Wqs[KC][HH + 4];      // d-major, transposed
    __shared__ float Wks[KC][HH + 4];
    __shared__ float red[TM][17];

    const int tid = threadIdx.x;
    const int tx = tid & 15;
    const int ty = tid >> 4;
    const int rowb = blockIdx.x * TM;

    unsigned long long acc[4][8];
#pragma unroll
    for (int i = 0; i < 4; i++)
#pragma unroll
        for (int j = 0; j < 8; j++) acc[i][j] = 0ull;

    const int rid = tid & 63;     // row within tile for X loads
    const int qd  = tid >> 6;     // which float4 of the 16-d chunk (0..3)

    for (int c = 0; c < DD / KC; c++) {
        const int d0 = c * KC;

        // ---- stage loads into registers (X tile + W tile) ----
        const float4 q4 = *reinterpret_cast<const float4*>(&Q[(rowb + rid) * DD + d0 + qd * 4]);
        const float4 k4 = *reinterpret_cast<const float4*>(&K[(rowb + rid) * DD + d0 + qd * 4]);
        const int h = tid;  // one W row per thread
        const float4 wq0 = *reinterpret_cast<const float4*>(&Wq[h * DD + d0 + 0]);
        const float4 wq1 = *reinterpret_cast<const float4*>(&Wq[h * DD + d0 + 4]);
        const float4 wq2 = *reinterpret_cast<const float4*>(&Wq[h * DD + d0 + 8]);
        const float4 wq3 = *reinterpret_cast<const float4*>(&Wq[h * DD + d0 + 12]);
        const float4 wk0 = *reinterpret_cast<const float4*>(&Wk[h * DD + d0 + 0]);
        const float4 wk1 = *reinterpret_cast<const float4*>(&Wk[h * DD + d0 + 4]);
        const float4 wk2 = *reinterpret_cast<const float4*>(&Wk[h * DD + d0 + 8]);
        const float4 wk3 = *reinterpret_cast<const float4*>(&Wk[h * DD + d0 + 12]);

        __syncthreads();   // previous chunk's smem consumers done

        // ---- transposed stores (conflict-free: consecutive lanes, same d) ----
        Xq[qd * 4 + 0][rid] = q4.x;  Xq[qd * 4 + 1][rid] = q4.y;
        Xq[qd * 4 + 2][rid] = q4.z;  Xq[qd * 4 + 3][rid] = q4.w;
        Xk[qd * 4 + 0][rid] = k4.x;  Xk[qd * 4 + 1][rid] = k4.y;
        Xk[qd * 4 + 2][rid] = k4.z;  Xk[qd * 4 + 3][rid] = k4.w;

        Wqs[0][h] = wq0.x;  Wqs[1][h] = wq0.y;  Wqs[2][h] = wq0.z;  Wqs[3][h] = wq0.w;
        Wqs[4][h] = wq1.x;  Wqs[5][h] = wq1.y;  Wqs[6][h] = wq1.z;  Wqs[7][h] = wq1.w;
        Wqs[8][h] = wq2.x;  Wqs[9][h] = wq2.y;  Wqs[10][h] = wq2.z; Wqs[11][h] = wq2.w;
        Wqs[12][h] = wq3.x; Wqs[13][h] = wq3.y; Wqs[14][h] = wq3.z; Wqs[15][h] = wq3.w;
        Wks[0][h] = wk0.x;  Wks[1][h] = wk0.y;  Wks[2][h] = wk0.z;  Wks[3][h] = wk0.w;
        Wks[4][h] = wk1.x;  Wks[5][h] = wk1.y;  Wks[6][h] = wk1.z;  Wks[7][h] = wk1.w;
        Wks[8][h] = wk2.x;  Wks[9][h] = wk2.y;  Wks[10][h] = wk2.z; Wks[11][h] = wk2.w;
        Wks[12][h] = wk3.x; Wks[13][h] = wk3.y; Wks[14][h] = wk3.z; Wks[15][h] = wk3.w;

        __syncthreads();

        // ---- compute ----
#pragma unroll
        for (int d = 0; d < KC; d++) {
            const float4 xq4 = *reinterpret_cast<const float4*>(&Xq[d][ty * 4]);
            const float4 xk4 = *reinterpret_cast<const float4*>(&Xk[d][ty * 4]);
            unsigned long long xq2[4], xk2[4];
            xq2[0] = bcast2(xq4.x); xq2[1] = bcast2(xq4.y);
            xq2[2] = bcast2(xq4.z); xq2[3] = bcast2(xq4.w);
            xk2[0] = bcast2(xk4.x); xk2[1] = bcast2(xk4.y);
            xk2[2] = bcast2(xk4.z); xk2[3] = bcast2(xk4.w);

            unsigned long long wqr[8], wkr[8];
#pragma unroll
            for (int j = 0; j < 8; j++) {
                wqr[j] = *reinterpret_cast<const unsigned long long*>(&Wqs[d][tx * 2 + 32 * j]);
                wkr[j] = *reinterpret_cast<const unsigned long long*>(&Wks[d][tx * 2 + 32 * j]);
            }
#pragma unroll
            for (int i = 0; i < 4; i++)
#pragma unroll
                for (int j = 0; j < 8; j++) {
                    fma2(acc[i][j], xq2[i], wqr[j]);
                    fma2(acc[i][j], xk2[i], wkr[j]);
                }
        }
    }

    // ---- epilogue: tanh, dot with Wv, reduce over tx ----
    float s[4] = {0.f, 0.f, 0.f, 0.f};
#pragma unroll
    for (int j = 0; j < 8; j++) {
        const float wv0 = Wv[tx * 2 + 32 * j];
        const float wv1 = Wv[tx * 2 + 32 * j + 1];
#pragma unroll
        for (int i = 0; i < 4; i++) {
            float lo, hi;
            unpack2(acc[i][j], lo, hi);
            s[i] += wv0 * tanhf(lo) + wv1 * tanhf(hi);
        }
    }
    __syncthreads();
#pragma unroll
    for (int i = 0; i < 4; i++) red[ty * 4 + i][tx] = s[i];
    __syncthreads();
    if (tid < TM) {
        float t = 0.f;
#pragma unroll
        for (int j = 0; j < 16; j++) t += red[tid][j];
        g_scores[rowb + tid] = t;
    }
}

// =====================================================================
// Kernel B: per-batch max / first-occurrence argmax / softmax denominator.
// Also writes argmax (as float) to the tail of d_out if there is room.
// =====================================================================
__global__ void stats_kernel(float* __restrict__ out, int out_size)
{
    const int b = blockIdx.x;
    const int tid = threadIdx.x;
    const float* s = g_scores + (long)b * NN;

    float m = -INFINITY;
    int mi = 0;
    for (int n = tid; n < NN; n += 256) {
        const float v = s[n];
        if (v > m) { m = v; mi = n; }
    }
    __shared__ float sm[256];
    __shared__ int   si[256];
    sm[tid] = m; si[tid] = mi;
    __syncthreads();
    for (int o = 128; o > 0; o >>= 1) {
        if (tid < o) {
            const float v = sm[tid + o]; const int vi = si[tid + o];
            if (v > sm[tid] || (v == sm[tid] && vi < si[tid])) { sm[tid] = v; si[tid] = vi; }
        }
        __syncthreads();
    }
    const float mx = sm[0];
    const int amax = si[0];
    __syncthreads();

    float acc = 0.f;
    for (int n = tid; n < NN; n += 256) acc += expf(s[n] - mx);
    sm[tid] = acc;
    __syncthreads();
    for (int o = 128; o > 0; o >>= 1) {
        if (tid < o) sm[tid] += sm[tid + o];
        __syncthreads();
    }
    if (tid == 0) {
        g_bmax[b] = mx;
        g_bden[b] = sm[0];
        if (out_size >= BB * DD + BB) out[BB * DD + b] = (float)amax;
    }
}

// =====================================================================
// Kernel C: partial weighted sums  g_part[b][chunk][d] = sum_{n in chunk} alpha[n] * V[b,n,d]
// Grid: (NCHUNK, BB). Deterministic (no atomics).
// =====================================================================
__global__ void weighted_kernel(const float* __restrict__ V)
{
    const int chunk = blockIdx.x;
    const int b = blockIdx.y;
    const int tid = threadIdx.x;

    __shared__ float w[256];
    const float mx = g_bmax[b];
    const float inv = 1.0f / g_bden[b];
    const int n0 = chunk * 256;
    w[tid] = expf(g_scores[(long)b * NN + n0 + tid] - mx) * inv;
    __syncthreads();

    const float* Vp = V + ((long)b * NN + n0) * DD + tid;
    float acc = 0.f;
#pragma unroll 8
    for (int n = 0; n < 256; n++) acc += w[n] * Vp[(long)n * DD];
    g_part[b][chunk][tid] = acc;
}

// =====================================================================
// Kernel D: reduce partials -> out[b, d]
// =====================================================================
__global__ void finalize_kernel(float* __restrict__ out)
{
    const int b = blockIdx.x;
    const int tid = threadIdx.x;
    float acc = 0.f;
#pragma unroll
    for (int c = 0; c < NCHUNK; c++) acc += g_part[b][c][tid];
    out[b * DD + tid] = acc;
}

// =====================================================================
extern "C" void kernel_launch(void* const* d_in, const int* in_sizes, int n_in,
                              void* d_out, int out_size)
{
    const float* Q  = (const float*)d_in[0];
    const float* K  = (const float*)d_in[1];
    const float* V  = (const float*)d_in[2];
    const float* Wq = (const float*)d_in[3];
    const float* Wk = (const float*)d_in[4];
    const float* Wv = (const float*)d_in[5];
    float* out = (float*)d_out;

    scores_kernel<<<MTOT / TM, 256>>>(Q, K, Wq, Wk, Wv);
    stats_kernel<<<BB, 256>>>(out, out_size);
    weighted_kernel<<<dim3(NCHUNK, BB), 256>>>(V);
    finalize_kernel<<<BB, DD>>>(out);
}

// round 3
// speedup vs baseline: 1.9463x; 1.9463x over previous
#include <cuda_runtime.h>
#include <cuda_bf16.h>
#include <cstdint>
#include <math.h>

// Shapes fixed by the reference: B=32, N=4096, D=256, H=256
#define BB 32
#define NN 4096
#define DD 256
#define HH 256
#define MTOT (BB * NN)          // 131072 rows
#define TILE_M 128
#define NTILES (MTOT / TILE_M)  // 1024
#define NCHUNK 16
#define KC 32                   // d-chunk
#define SA 40                   // padded smem row stride in bf16 elems (80 B)

// ---------------- device scratch (no allocation allowed) ----------------
__device__ float g_scores[MTOT];
__device__ float g_bmax[BB];
__device__ float g_bden[BB];
__device__ float g_part[BB][NCHUNK][DD];
__device__ __nv_bfloat16 g_Wqh[HH * DD];
__device__ __nv_bfloat16 g_Wql[HH * DD];
__device__ __nv_bfloat16 g_Wkh[HH * DD];
__device__ __nv_bfloat16 g_Wkl[HH * DD];

// ---------------- helpers ----------------
static __device__ __forceinline__ uint32_t smem_u32(const void* p) {
    uint32_t a;
    asm("{ .reg .u64 t; cvta.to.shared.u64 t, %1; cvt.u32.u64 %0, t; }"
        : "=r"(a) : "l"(p));
    return a;
}

static __device__ __forceinline__ void ldsm_x4(uint32_t& r0, uint32_t& r1,
                                               uint32_t& r2, uint32_t& r3,
                                               uint32_t addr) {
    asm volatile("ldmatrix.sync.aligned.m8n8.x4.shared.b16 {%0,%1,%2,%3}, [%4];"
                 : "=r"(r0), "=r"(r1), "=r"(r2), "=r"(r3) : "r"(addr));
}

static __device__ __forceinline__ void mma_bf16(float* c, const uint32_t* a,
                                                uint32_t b0, uint32_t b1) {
    asm volatile(
        "mma.sync.aligned.m16n8k16.row.col.f32.bf16.bf16.f32 "
        "{%0,%1,%2,%3}, {%4,%5,%6,%7}, {%8,%9}, {%0,%1,%2,%3};"
        : "+f"(c[0]), "+f"(c[1]), "+f"(c[2]), "+f"(c[3])
        : "r"(a[0]), "r"(a[1]), "r"(a[2]), "r"(a[3]), "r"(b0), "r"(b1));
}

static __device__ __forceinline__ uint32_t pack_bf(__nv_bfloat16 a, __nv_bfloat16 b) {
    __nv_bfloat162 t(a, b);
    return *reinterpret_cast<uint32_t*>(&t);
}

// Accurate fp32 tanh (Eigen-style rational, ~few-ulp in [-7.9, 7.9]).
static __device__ __forceinline__ float tanh_fast(float x) {
    float xc = fminf(fmaxf(x, -7.90531110763549805f), 7.90531110763549805f);
    float x2 = xc * xc;
    float p = fmaf(x2, -2.76076847742355e-16f, 2.00018790482477e-13f);
    p = fmaf(p, x2, -8.60467152213735e-11f);
    p = fmaf(p, x2, 5.12229709037114e-08f);
    p = fmaf(p, x2, 1.48572235717979e-05f);
    p = fmaf(p, x2, 6.37261928875436e-04f);
    p = fmaf(p, x2, 4.89352455891786e-03f);
    float q = fmaf(x2, 1.19825839466702e-06f, 1.18534705686654e-04f);
    q = fmaf(q, x2, 2.26843463243900e-03f);
    q = fmaf(q, x2, 4.89352518554385e-03f);
    return __fdividef(xc * p, q);
}

// =====================================================================
// Setup: split Wq/Wk fp32 -> (hi, lo) bf16 pairs in global scratch.
// =====================================================================
__global__ void wsplit_kernel(const float* __restrict__ Wq, const float* __restrict__ Wk) {
    const int i = blockIdx.x * 256 + threadIdx.x;
    const float q = Wq[i];
    const float k = Wk[i];
    __nv_bfloat16 qh = __float2bfloat16(q);
    __nv_bfloat16 kh = __float2bfloat16(k);
    g_Wqh[i] = qh;  g_Wql[i] = __float2bfloat16(q - __bfloat162float(qh));
    g_Wkh[i] = kh;  g_Wkl[i] = __float2bfloat16(k - __bfloat162float(kh));
}

// =====================================================================
// Scores via legacy HMMA (mma.sync bf16, 3-pass split for fp32 accuracy):
//   Z[128,256] = Q·Wq^T + K·Wk^T ; scores = Wv · tanh(Z)
// CTA: 256 thr = 8 warps; warp tile 32(m) x 64(n); two 128-wide h-blocks.
// =====================================================================
__global__ __launch_bounds__(256)
void scores_mma_kernel(const float* __restrict__ Q, const float* __restrict__ K,
                       const float* __restrict__ Wv) {
    __shared__ alignas(128) __nv_bfloat16 sAh_[TILE_M * SA];
    __shared__ alignas(128) __nv_bfloat16 sAl_[TILE_M * SA];
    __shared__ alignas(128) __nv_bfloat16 sBh_[128 * SA];
    __shared__ alignas(128) __nv_bfloat16 sBl_[128 * SA];
    __shared__ float s_wv[HH];
    __shared__ float s_red[2][TILE_M];

    const int tid = threadIdx.x;
    const int wid = tid >> 5;
    const int lane = tid & 31;
    const int warp_m = wid & 3;      // 4 m-groups of 32 rows
    const int warp_n = wid >> 2;     // 2 n-groups of 64 cols
    const int m0 = blockIdx.x * TILE_M;

    s_wv[tid] = Wv[tid];

    const uint32_t aH = smem_u32(sAh_), aL = smem_u32(sAl_);
    const uint32_t bH = smem_u32(sBh_), bL = smem_u32(sBl_);

    // ldmatrix offsets (bytes), precomputed per lane
    uint32_t aoff[2][2];   // [mi][ks]
#pragma unroll
    for (int mi = 0; mi < 2; mi++)
#pragma unroll
        for (int ks = 0; ks < 2; ks++)
            aoff[mi][ks] = (uint32_t)((warp_m * 32 + mi * 16 + (lane & 15)) * (SA * 2)
                                      + (ks * 16 + ((lane >> 4) * 8)) * 2);
    uint32_t boff[4][2];   // [ntp][ks]: ntp covers n-tiles {2ntp, 2ntp+1}
#pragma unroll
    for (int ntp = 0; ntp < 4; ntp++)
#pragma unroll
        for (int ks = 0; ks < 2; ks++)
            boff[ntp][ks] = (uint32_t)((warp_n * 64 + ntp * 16 + (lane & 7) + ((lane >> 4) << 3)) * (SA * 2)
                                       + ks * 32 + ((lane >> 3) & 1) * 16);

    float sp[4] = {0.f, 0.f, 0.f, 0.f};   // per-lane row partial scores

#pragma unroll 1
    for (int hb = 0; hb < 2; hb++) {
        float c[2][8][4];
#pragma unroll
        for (int mi = 0; mi < 2; mi++)
#pragma unroll
            for (int nt = 0; nt < 8; nt++)
#pragma unroll
                for (int r = 0; r < 4; r++) c[mi][nt][r] = 0.f;

#pragma unroll 1
        for (int src = 0; src < 2; src++) {
            const float* X = src ? K : Q;
            const __nv_bfloat16* WhG = src ? g_Wkh : g_Wqh;
            const __nv_bfloat16* WlG = src ? g_Wkl : g_Wql;

#pragma unroll 1
            for (int ch = 0; ch < DD / KC; ch++) {
                const int d0 = ch * KC;

                // ---- stage global loads ----
                float4 av[4];
#pragma unroll
                for (int j = 0; j < 4; j++) {
                    const int t = tid + 256 * j;
                    const int r = t >> 3, c4 = t & 7;
                    av[j] = *reinterpret_cast<const float4*>(
                        X + (size_t)(m0 + r) * DD + d0 + c4 * 4);
                }
                uint4 bvh[2], bvl[2];
#pragma unroll
                for (int j = 0; j < 2; j++) {
                    const int t = tid + 256 * j;
                    const int r = t >> 2, c4 = t & 3;
                    const size_t off = (size_t)(hb * 128 + r) * DD + d0 + c4 * 8;
                    bvh[j] = *reinterpret_cast<const uint4*>(WhG + off);
                    bvl[j] = *reinterpret_cast<const uint4*>(WlG + off);
                }

                __syncthreads();   // previous chunk's smem consumers done

                // ---- A: split fp32 -> bf16 hi/lo, store padded smem ----
#pragma unroll
                for (int j = 0; j < 4; j++) {
                    const int t = tid + 256 * j;
                    const int r = t >> 3, c4 = t & 7;
                    const float4 v = av[j];
                    const __nv_bfloat16 bx = __float2bfloat16(v.x);
                    const __nv_bfloat16 by = __float2bfloat16(v.y);
                    const __nv_bfloat16 bz = __float2bfloat16(v.z);
                    const __nv_bfloat16 bw = __float2bfloat16(v.w);
                    uint2 hv, lv;
                    hv.x = pack_bf(bx, by);  hv.y = pack_bf(bz, bw);
                    lv.x = pack_bf(__float2bfloat16(v.x - __bfloat162float(bx)),
                                   __float2bfloat16(v.y - __bfloat162float(by)));
                    lv.y = pack_bf(__float2bfloat16(v.z - __bfloat162float(bz)),
                                   __float2bfloat16(v.w - __bfloat162float(bw)));
                    *reinterpret_cast<uint2*>(&sAh_[r * SA + c4 * 4]) = hv;
                    *reinterpret_cast<uint2*>(&sAl_[r * SA + c4 * 4]) = lv;
                }
                // ---- B: copy pre-split weights ----
#pragma unroll
                for (int j = 0; j < 2; j++) {
                    const int t = tid + 256 * j;
                    const int r = t >> 2, c4 = t & 3;
                    *reinterpret_cast<uint4*>(&sBh_[r * SA + c4 * 8]) = bvh[j];
                    *reinterpret_cast<uint4*>(&sBl_[r * SA + c4 * 8]) = bvl[j];
                }
                __syncthreads();

                // ---- 3 passes: hi*hi, hi*lo, lo*hi ----
#pragma unroll
                for (int p = 0; p < 3; p++) {
                    const uint32_t aBase = (p == 2) ? aL : aH;
                    const uint32_t bBase = (p == 1) ? bL : bH;
#pragma unroll
                    for (int ks = 0; ks < 2; ks++) {
                        uint32_t a0[4], a1[4];
                        ldsm_x4(a0[0], a0[1], a0[2], a0[3], aBase + aoff[0][ks]);
                        ldsm_x4(a1[0], a1[1], a1[2], a1[3], aBase + aoff[1][ks]);
#pragma unroll
                        for (int ntp = 0; ntp < 4; ntp++) {
                            uint32_t b0, b1, b2, b3;
                            ldsm_x4(b0, b1, b2, b3, bBase + boff[ntp][ks]);
                            mma_bf16(c[0][ntp * 2 + 0], a0, b0, b1);
                            mma_bf16(c[0][ntp * 2 + 1], a0, b2, b3);
                            mma_bf16(c[1][ntp * 2 + 0], a1, b0, b1);
                            mma_bf16(c[1][ntp * 2 + 1], a1, b2, b3);
                        }
                    }
                }
            }
        }

        // ---- epilogue for this h-block: tanh + Wv dot into sp ----
#pragma unroll
        for (int mi = 0; mi < 2; mi++)
#pragma unroll
            for (int nt = 0; nt < 8; nt++) {
                const int col = hb * 128 + warp_n * 64 + nt * 8 + (lane & 3) * 2;
                const float w0 = s_wv[col], w1 = s_wv[col + 1];
                sp[mi * 2 + 0] = fmaf(w0, tanh_fast(c[mi][nt][0]),
                                 fmaf(w1, tanh_fast(c[mi][nt][1]), sp[mi * 2 + 0]));
                sp[mi * 2 + 1] = fmaf(w0, tanh_fast(c[mi][nt][2]),
                                 fmaf(w1, tanh_fast(c[mi][nt][3]), sp[mi * 2 + 1]));
            }
    }

    // ---- reduce: 4 lanes sharing a row -> butterfly; then across warp_n ----
#pragma unroll
    for (int i = 0; i < 4; i++) {
        sp[i] += __shfl_xor_sync(0xFFFFFFFFu, sp[i], 1);
        sp[i] += __shfl_xor_sync(0xFFFFFFFFu, sp[i], 2);
    }
    __syncthreads();   // done with mma smem; safe ordering before s_red reuse
    if ((lane & 3) == 0) {
#pragma unroll
        for (int mi = 0; mi < 2; mi++)
#pragma unroll
            for (int half = 0; half < 2; half++) {
                const int row = warp_m * 32 + mi * 16 + half * 8 + (lane >> 2);
                s_red[warp_n][row] = sp[mi * 2 + half];
            }
    }
    __syncthreads();
    if (tid < TILE_M)
        g_scores[m0 + tid] = s_red[0][tid] + s_red[1][tid];
}

// =====================================================================
// Kernel B: per-batch max / first-occurrence argmax / softmax denominator.
// =====================================================================
__global__ void stats_kernel(float* __restrict__ out, int out_size) {
    const int b = blockIdx.x;
    const int tid = threadIdx.x;
    const float* s = g_scores + (long)b * NN;

    float m = -INFINITY;
    int mi = 0;
    for (int n = tid; n < NN; n += 256) {
        const float v = s[n];
        if (v > m) { m = v; mi = n; }
    }
    __shared__ float sm[256];
    __shared__ int   si[256];
    sm[tid] = m; si[tid] = mi;
    __syncthreads();
    for (int o = 128; o > 0; o >>= 1) {
        if (tid < o) {
            const float v = sm[tid + o]; const int vi = si[tid + o];
            if (v > sm[tid] || (v == sm[tid] && vi < si[tid])) { sm[tid] = v; si[tid] = vi; }
        }
        __syncthreads();
    }
    const float mx = sm[0];
    const int amax = si[0];
    __syncthreads();

    float acc = 0.f;
    for (int n = tid; n < NN; n += 256) acc += expf(s[n] - mx);
    sm[tid] = acc;
    __syncthreads();
    for (int o = 128; o > 0; o >>= 1) {
        if (tid < o) sm[tid] += sm[tid + o];
        __syncthreads();
    }
    if (tid == 0) {
        g_bmax[b] = mx;
        g_bden[b] = sm[0];
        if (out_size >= BB * DD + BB) out[BB * DD + b] = (float)amax;
    }
}

// =====================================================================
// Kernel C: partial weighted sums (deterministic, no atomics)
// =====================================================================
__global__ void weighted_kernel(const float* __restrict__ V) {
    const int chunk = blockIdx.x;
    const int b = blockIdx.y;
    const int tid = threadIdx.x;

    __shared__ float w[256];
    const float mx = g_bmax[b];
    const float inv = 1.0f / g_bden[b];
    const int n0 = chunk * 256;
    w[tid] = expf(g_scores[(long)b * NN + n0 + tid] - mx) * inv;
    __syncthreads();

    const float* Vp = V + ((long)b * NN + n0) * DD + tid;
    float acc = 0.f;
#pragma unroll 8
    for (int n = 0; n < 256; n++) acc += w[n] * Vp[(long)n * DD];
    g_part[b][chunk][tid] = acc;
}

// =====================================================================
// Kernel D: reduce partials -> out[b, d]
// =====================================================================
__global__ void finalize_kernel(float* __restrict__ out) {
    const int b = blockIdx.x;
    const int tid = threadIdx.x;
    float acc = 0.f;
#pragma unroll
    for (int c = 0; c < NCHUNK; c++) acc += g_part[b][c][tid];
    out[b * DD + tid] = acc;
}

// =====================================================================
extern "C" void kernel_launch(void* const* d_in, const int* in_sizes, int n_in,
                              void* d_out, int out_size) {
    const float* Q  = (const float*)d_in[0];
    const float* K  = (const float*)d_in[1];
    const float* V  = (const float*)d_in[2];
    const float* Wq = (const float*)d_in[3];
    const float* Wk = (const float*)d_in[4];
    const float* Wv = (const float*)d_in[5];
    float* out = (float*)d_out;

    wsplit_kernel<<<HH * DD / 256, 256>>>(Wq, Wk);
    scores_mma_kernel<<<NTILES, 256>>>(Q, K, Wv);
    stats_kernel<<<BB, 256>>>(out, out_size);
    weighted_kernel<<<dim3(NCHUNK, BB), 256>>>(V);
    finalize_kernel<<<BB, DD>>>(out);
}

// round 5
// speedup vs baseline: 2.3210x; 1.1925x over previous
#include <cuda_runtime.h>
#include <cuda_bf16.h>
#include <cstdint>
#include <math.h>

// Shapes fixed by the reference: B=32, N=4096, D=256, H=256
#define BB 32
#define NN 4096
#define DD 256
#define HH 256
#define MTOT (BB * NN)          // 131072 rows
#define TILE_M 128
#define NTILES (MTOT / TILE_M)  // 1024
#define NCHUNK 32
#define KC 32                   // d-chunk
#define SA 40                   // padded smem row stride in bf16 elems (80 B, 16B-multiple)
#define TILE_BYTES (128 * SA * 2)   // 10240 B per tile
#define DYN_SMEM (8 * TILE_BYTES)   // 2 bufs x (Ah,Al,Bh,Bl) = 81920 B

// ---------------- device scratch (no allocation allowed) ----------------
__device__ float g_scores[MTOT];
__device__ float g_bmax[BB];
__device__ float g_bden[BB];
__device__ float g_part[BB][NCHUNK][DD];
__device__ __align__(16) __nv_bfloat16 g_Wqh[HH * DD];
__device__ __align__(16) __nv_bfloat16 g_Wql[HH * DD];
__device__ __align__(16) __nv_bfloat16 g_Wkh[HH * DD];
__device__ __align__(16) __nv_bfloat16 g_Wkl[HH * DD];

// ---------------- helpers ----------------
static __device__ __forceinline__ uint32_t smem_u32(const void* p) {
    uint32_t a;
    asm("{ .reg .u64 t; cvta.to.shared.u64 t, %1; cvt.u32.u64 %0, t; }"
        : "=r"(a) : "l"(p));
    return a;
}

static __device__ __forceinline__ void ldsm_x4(uint32_t& r0, uint32_t& r1,
                                               uint32_t& r2, uint32_t& r3,
                                               uint32_t addr) {
    asm volatile("ldmatrix.sync.aligned.m8n8.x4.shared.b16 {%0,%1,%2,%3}, [%4];"
                 : "=r"(r0), "=r"(r1), "=r"(r2), "=r"(r3) : "r"(addr));
}

static __device__ __forceinline__ void mma_bf16(float* c, const uint32_t* a,
                                                uint32_t b0, uint32_t b1) {
    asm volatile(
        "mma.sync.aligned.m16n8k16.row.col.f32.bf16.bf16.f32 "
        "{%0,%1,%2,%3}, {%4,%5,%6,%7}, {%8,%9}, {%0,%1,%2,%3};"
        : "+f"(c[0]), "+f"(c[1]), "+f"(c[2]), "+f"(c[3])
        : "r"(a[0]), "r"(a[1]), "r"(a[2]), "r"(a[3]), "r"(b0), "r"(b1));
}

static __device__ __forceinline__ void cp_async16(uint32_t saddr, const void* gptr) {
    asm volatile("cp.async.cg.shared.global [%0], [%1], 16;"
                 :: "r"(saddr), "l"(gptr) : "memory");
}
#define CP_COMMIT() asm volatile("cp.async.commit_group;" ::: "memory")
#define CP_WAIT0()  asm volatile("cp.async.wait_group 0;" ::: "memory")

static __device__ __forceinline__ uint32_t pack_bf(__nv_bfloat16 a, __nv_bfloat16 b) {
    __nv_bfloat162 t(a, b);
    return *reinterpret_cast<uint32_t*>(&t);
}

// Accurate fp32 tanh (Eigen-style rational, ~few-ulp in [-7.9, 7.9]).
static __device__ __forceinline__ float tanh_fast(float x) {
    float xc = fminf(fmaxf(x, -7.90531110763549805f), 7.90531110763549805f);
    float x2 = xc * xc;
    float p = fmaf(x2, -2.76076847742355e-16f, 2.00018790482477e-13f);
    p = fmaf(p, x2, -8.60467152213735e-11f);
    p = fmaf(p, x2, 5.12229709037114e-08f);
    p = fmaf(p, x2, 1.48572235717979e-05f);
    p = fmaf(p, x2, 6.37261928875436e-04f);
    p = fmaf(p, x2, 4.89352455891786e-03f);
    float q = fmaf(x2, 1.19825839466702e-06f, 1.18534705686654e-04f);
    q = fmaf(q, x2, 2.26843463243900e-03f);
    q = fmaf(q, x2, 4.89352518554385e-03f);
    return __fdividef(xc * p, q);
}

// =====================================================================
// Setup: split Wq/Wk fp32 -> (hi, lo) bf16 pairs in global scratch.
// =====================================================================
__global__ void wsplit_kernel(const float* __restrict__ Wq, const float* __restrict__ Wk) {
    const int i = blockIdx.x * 256 + threadIdx.x;
    const float q = Wq[i];
    const float k = Wk[i];
    __nv_bfloat16 qh = __float2bfloat16(q);
    __nv_bfloat16 kh = __float2bfloat16(k);
    g_Wqh[i] = qh;  g_Wql[i] = __float2bfloat16(q - __bfloat162float(qh));
    g_Wkh[i] = kh;  g_Wkl[i] = __float2bfloat16(k - __bfloat162float(kh));
}

// =====================================================================
// Scores via HMMA (mma.sync bf16, 3-pass split for fp32 accuracy),
// double-buffered software pipeline:
//   STS A(cur); wait B(cur); sync; prefetch A/B(next); MMA(cur)
// Hazards: buffers alternate; MMA(it-1) on buf^1 precedes sync(it) in all
// warps' program order, so writes to buf^1 after sync(it) are safe.
// =====================================================================
__global__ __launch_bounds__(256, 2)
void scores_mma_kernel(const float* __restrict__ Q, const float* __restrict__ K,
                       const float* __restrict__ Wv) {
    extern __shared__ __align__(128) char dyn[];
    __shared__ float s_wv[HH];
    __shared__ float s_red[2][TILE_M];

    const int tid = threadIdx.x;
    const int lane = tid & 31;
    const int wid = tid >> 5;
    const int warp_m = wid & 3;      // 4 m-groups of 32 rows
    const int warp_n = wid >> 2;     // 2 n-groups of 64 cols
    const int m0 = blockIdx.x * TILE_M;

    s_wv[tid] = Wv[tid];

    const uint32_t base = smem_u32(dyn);
    // tile(buf, which): which: 0=Ah 1=Al 2=Bh 3=Bl
#define STILE(buf, w) (base + ((buf) * 4 + (w)) * TILE_BYTES)

    // per-lane ldmatrix byte offsets (within a tile)
    uint32_t aoff[2][2];
#pragma unroll
    for (int mi = 0; mi < 2; mi++)
#pragma unroll
        for (int ks = 0; ks < 2; ks++)
            aoff[mi][ks] = (uint32_t)((warp_m * 32 + mi * 16 + (lane & 15)) * (SA * 2)
                                      + (ks * 16 + ((lane >> 4) * 8)) * 2);
    uint32_t boff[4][2];
#pragma unroll
    for (int ntp = 0; ntp < 4; ntp++)
#pragma unroll
        for (int ks = 0; ks < 2; ks++)
            boff[ntp][ks] = (uint32_t)((warp_n * 64 + ntp * 16 + (lane & 7) + ((lane >> 4) << 3)) * (SA * 2)
                                       + ks * 32 + ((lane >> 3) & 1) * 16);

    // A-staging thread geometry
    const int ar = tid >> 3;         // row 0..31 (x4 j-steps cover 128)
    const int ac4 = tid & 7;         // float4 within 32-d chunk
    // B cp.async thread geometry
    const int br = tid >> 2;         // row 0..63 (x2 j-steps cover 128)
    const int bc8 = tid & 3;         // uint4 (8 bf16) within chunk

    float sp[4] = {0.f, 0.f, 0.f, 0.f};

#pragma unroll 1
    for (int hb = 0; hb < 2; hb++) {
        float c[2][8][4];
#pragma unroll
        for (int mi = 0; mi < 2; mi++)
#pragma unroll
            for (int nt = 0; nt < 8; nt++)
#pragma unroll
                for (int r = 0; r < 4; r++) c[mi][nt][r] = 0.f;

        uint32_t ah[8], al[8];   // staged converted A for "next" chunk

        // ---- prestage it=0 (src=Q, d0=0) ----
        {
#pragma unroll
            for (int j = 0; j < 4; j++) {
                const int r = ar + 32 * j;
                const float4 v = *reinterpret_cast<const float4*>(
                    Q + (size_t)(m0 + r) * DD + 0 + ac4 * 4);
                const __nv_bfloat16 bx = __float2bfloat16(v.x);
                const __nv_bfloat16 by = __float2bfloat16(v.y);
                const __nv_bfloat16 bz = __float2bfloat16(v.z);
                const __nv_bfloat16 bw = __float2bfloat16(v.w);
                ah[2*j]   = pack_bf(bx, by);
                ah[2*j+1] = pack_bf(bz, bw);
                al[2*j]   = pack_bf(__float2bfloat16(v.x - __bfloat162float(bx)),
                                    __float2bfloat16(v.y - __bfloat162float(by)));
                al[2*j+1] = pack_bf(__float2bfloat16(v.z - __bfloat162float(bz)),
                                    __float2bfloat16(v.w - __bfloat162float(bw)));
            }
#pragma unroll
            for (int j = 0; j < 2; j++) {
                const int r = br + 64 * j;
                const size_t goff = (size_t)(hb * 128 + r) * DD + 0 + bc8 * 8;
                const uint32_t soff = (uint32_t)(r * SA + bc8 * 8) * 2;
                cp_async16(STILE(0, 2) + soff, g_Wqh + goff);
                cp_async16(STILE(0, 3) + soff, g_Wql + goff);
            }
            CP_COMMIT();
        }

#pragma unroll 1
        for (int it = 0; it < 16; it++) {
            const int buf = it & 1;

            // ---- STS staged A ----
#pragma unroll
            for (int j = 0; j < 4; j++) {
                const int r = ar + 32 * j;
                const uint32_t soff = (uint32_t)(r * SA + ac4 * 4) * 2;
                asm volatile("st.shared.v2.u32 [%0], {%1, %2};"
                             :: "r"(STILE(buf, 0) + soff), "r"(ah[2*j]), "r"(ah[2*j+1]));
                asm volatile("st.shared.v2.u32 [%0], {%1, %2};"
                             :: "r"(STILE(buf, 1) + soff), "r"(al[2*j]), "r"(al[2*j+1]));
            }
            CP_WAIT0();          // B(it) delivered
            __syncthreads();

            // ---- prefetch (it+1): LDG+convert A to regs, cp.async B ----
            if (it < 15) {
                const int nit = it + 1;
                const int nsrc = nit >> 3;
                const int nd0 = (nit & 7) * KC;
                const float* X = nsrc ? K : Q;
                const __nv_bfloat16* WhG = nsrc ? g_Wkh : g_Wqh;
                const __nv_bfloat16* WlG = nsrc ? g_Wkl : g_Wql;
#pragma unroll
                for (int j = 0; j < 2; j++) {
                    const int r = br + 64 * j;
                    const size_t goff = (size_t)(hb * 128 + r) * DD + nd0 + bc8 * 8;
                    const uint32_t soff = (uint32_t)(r * SA + bc8 * 8) * 2;
                    cp_async16(STILE(buf ^ 1, 2) + soff, WhG + goff);
                    cp_async16(STILE(buf ^ 1, 3) + soff, WlG + goff);
                }
                CP_COMMIT();
#pragma unroll
                for (int j = 0; j < 4; j++) {
                    const int r = ar + 32 * j;
                    const float4 v = *reinterpret_cast<const float4*>(
                        X + (size_t)(m0 + r) * DD + nd0 + ac4 * 4);
                    const __nv_bfloat16 bx = __float2bfloat16(v.x);
                    const __nv_bfloat16 by = __float2bfloat16(v.y);
                    const __nv_bfloat16 bz = __float2bfloat16(v.z);
                    const __nv_bfloat16 bw = __float2bfloat16(v.w);
                    ah[2*j]   = pack_bf(bx, by);
                    ah[2*j+1] = pack_bf(bz, bw);
                    al[2*j]   = pack_bf(__float2bfloat16(v.x - __bfloat162float(bx)),
                                        __float2bfloat16(v.y - __bfloat162float(by)));
                    al[2*j+1] = pack_bf(__float2bfloat16(v.z - __bfloat162float(bz)),
                                        __float2bfloat16(v.w - __bfloat162float(bw)));
                }
            }

            // ---- 3 passes: hi*hi, hi*lo, lo*hi ----
#pragma unroll
            for (int p = 0; p < 3; p++) {
                const uint32_t aBase = (p == 2) ? STILE(buf, 1) : STILE(buf, 0);
                const uint32_t bBase = (p == 1) ? STILE(buf, 3) : STILE(buf, 2);
#pragma unroll
                for (int ks = 0; ks < 2; ks++) {
                    uint32_t a0[4], a1[4];
                    ldsm_x4(a0[0], a0[1], a0[2], a0[3], aBase + aoff[0][ks]);
                    ldsm_x4(a1[0], a1[1], a1[2], a1[3], aBase + aoff[1][ks]);
#pragma unroll
                    for (int ntp = 0; ntp < 4; ntp++) {
                        uint32_t b0, b1, b2, b3;
                        ldsm_x4(b0, b1, b2, b3, bBase + boff[ntp][ks]);
                        mma_bf16(c[0][ntp * 2 + 0], a0, b0, b1);
                        mma_bf16(c[0][ntp * 2 + 1], a0, b2, b3);
                        mma_bf16(c[1][ntp * 2 + 0], a1, b0, b1);
                        mma_bf16(c[1][ntp * 2 + 1], a1, b2, b3);
                    }
                }
            }
        }

        // ---- epilogue for this h-block: tanh + Wv dot into sp ----
#pragma unroll
        for (int mi = 0; mi < 2; mi++)
#pragma unroll
            for (int nt = 0; nt < 8; nt++) {
                const int col = hb * 128 + warp_n * 64 + nt * 8 + (lane & 3) * 2;
                const float w0 = s_wv[col], w1 = s_wv[col + 1];
                sp[mi * 2 + 0] = fmaf(w0, tanh_fast(c[mi][nt][0]),
                                 fmaf(w1, tanh_fast(c[mi][nt][1]), sp[mi * 2 + 0]));
                sp[mi * 2 + 1] = fmaf(w0, tanh_fast(c[mi][nt][2]),
                                 fmaf(w1, tanh_fast(c[mi][nt][3]), sp[mi * 2 + 1]));
            }
    }

    // ---- reduce: 4 lanes sharing a row -> butterfly; then across warp_n ----
#pragma unroll
    for (int i = 0; i < 4; i++) {
        sp[i] += __shfl_xor_sync(0xFFFFFFFFu, sp[i], 1);
        sp[i] += __shfl_xor_sync(0xFFFFFFFFu, sp[i], 2);
    }
    __syncthreads();
    if ((lane & 3) == 0) {
#pragma unroll
        for (int mi = 0; mi < 2; mi++)
#pragma unroll
            for (int half = 0; half < 2; half++) {
                const int row = warp_m * 32 + mi * 16 + half * 8 + (lane >> 2);
                s_red[warp_n][row] = sp[mi * 2 + half];
            }
    }
    __syncthreads();
    if (tid < TILE_M)
        g_scores[m0 + tid] = s_red[0][tid] + s_red[1][tid];
#undef STILE
}

// =====================================================================
// Kernel B: per-batch max / first-occurrence argmax / softmax denominator.
// =====================================================================
__global__ void stats_kernel(float* __restrict__ out, int out_size) {
    const int b = blockIdx.x;
    const int tid = threadIdx.x;
    const float* s = g_scores + (long)b * NN;

    float m = -INFINITY;
    int mi = 0;
    for (int n = tid; n < NN; n += 256) {
        const float v = s[n];
        if (v > m) { m = v; mi = n; }
    }
    __shared__ float sm[256];
    __shared__ int   si[256];
    sm[tid] = m; si[tid] = mi;
    __syncthreads();
    for (int o = 128; o > 0; o >>= 1) {
        if (tid < o) {
            const float v = sm[tid + o]; const int vi = si[tid + o];
            if (v > sm[tid] || (v == sm[tid] && vi < si[tid])) { sm[tid] = v; si[tid] = vi; }
        }
        __syncthreads();
    }
    const float mx = sm[0];
    const int amax = si[0];
    __syncthreads();

    float acc = 0.f;
    for (int n = tid; n < NN; n += 256) acc += expf(s[n] - mx);
    sm[tid] = acc;
    __syncthreads();
    for (int o = 128; o > 0; o >>= 1) {
        if (tid < o) sm[tid] += sm[tid + o];
        __syncthreads();
    }
    if (tid == 0) {
        g_bmax[b] = mx;
        g_bden[b] = sm[0];
        if (out_size >= BB * DD + BB) out[BB * DD + b] = (float)amax;
    }
}

// =====================================================================
// Kernel C: partial weighted sums (deterministic, no atomics)
// chunk = 128 rows; grid (NCHUNK=32, BB) = 1024 blocks
// =====================================================================
#define CROWS (NN / NCHUNK)   // 128
__global__ void weighted_kernel(const float* __restrict__ V) {
    const int chunk = blockIdx.x;
    const int b = blockIdx.y;
    const int tid = threadIdx.x;

    __shared__ float w[CROWS];
    const float mx = g_bmax[b];
    const float inv = 1.0f / g_bden[b];
    const int n0 = chunk * CROWS;
    if (tid < CROWS)
        w[tid] = expf(g_scores[(long)b * NN + n0 + tid] - mx) * inv;
    __syncthreads();

    const float* Vp = V + ((long)b * NN + n0) * DD + tid;
    float acc = 0.f;
#pragma unroll 8
    for (int n = 0; n < CROWS; n++) acc += w[n] * Vp[(long)n * DD];
    g_part[b][chunk][tid] = acc;
}

// =====================================================================
// Kernel D: reduce partials -> out[b, d]
// =====================================================================
__global__ void finalize_kernel(float* __restrict__ out) {
    const int b = blockIdx.x;
    const int tid = threadIdx.x;
    float acc = 0.f;
#pragma unroll
    for (int c = 0; c < NCHUNK; c++) acc += g_part[b][c][tid];
    out[b * DD + tid] = acc;
}

// =====================================================================
extern "C" void kernel_launch(void* const* d_in, const int* in_sizes, int n_in,
                              void* d_out, int out_size) {
    const float* Q  = (const float*)d_in[0];
    const float* K  = (const float*)d_in[1];
    const float* V  = (const float*)d_in[2];
    const float* Wq = (const float*)d_in[3];
    const float* Wk = (const float*)d_in[4];
    const float* Wv = (const float*)d_in[5];
    float* out = (float*)d_out;

    cudaFuncSetAttribute(scores_mma_kernel,
                         cudaFuncAttributeMaxDynamicSharedMemorySize, DYN_SMEM);

    wsplit_kernel<<<HH * DD / 256, 256>>>(Wq, Wk);
    scores_mma_kernel<<<NTILES, 256, DYN_SMEM>>>(Q, K, Wv);
    stats_kernel<<<BB, 256>>>(out, out_size);
    weighted_kernel<<<dim3(NCHUNK, BB), 256>>>(V);
    finalize_kernel<<<BB, DD>>>(out);
}

// round 8
// speedup vs baseline: 3.3654x; 1.4500x over previous
#include <cuda_runtime.h>
#include <cuda_fp16.h>
#include <cstdint>
#include <math.h>

// Shapes fixed by the reference: B=32, N=4096, D=256, H=256
#define BB 32
#define NN 4096
#define DD 256
#define HH 256
#define MTOT (BB * NN)          // 131072 rows
#define TILE_M 128
#define NTILES (MTOT / TILE_M)  // 1024
#define NCHUNK 32
#define KC 32                   // d-chunk
#define SA 40                   // padded smem row stride in fp16 elems (80 B, 16B-multiple)
#define TILE_BYTES (128 * SA * 2)   // 10240 B per tile
#define DYN_SMEM (6 * TILE_BYTES)   // 2 bufs x (Ah, Al, Bh) = 61440 B

// ---------------- device scratch (no allocation allowed) ----------------
__device__ float g_scores[MTOT];
__device__ float g_bmax[BB];
__device__ float g_bden[BB];
__device__ float g_part[BB][NCHUNK][DD];
__device__ __align__(16) __half g_Wqh[HH * DD];
__device__ __align__(16) __half g_Wkh[HH * DD];

// ---------------- helpers ----------------
static __device__ __forceinline__ uint32_t smem_u32(const void* p) {
    uint32_t a;
    asm("{ .reg .u64 t; cvta.to.shared.u64 t, %1; cvt.u32.u64 %0, t; }"
        : "=r"(a) : "l"(p));
    return a;
}

static __device__ __forceinline__ void ldsm_x4(uint32_t& r0, uint32_t& r1,
                                               uint32_t& r2, uint32_t& r3,
                                               uint32_t addr) {
    asm volatile("ldmatrix.sync.aligned.m8n8.x4.shared.b16 {%0,%1,%2,%3}, [%4];"
                 : "=r"(r0), "=r"(r1), "=r"(r2), "=r"(r3) : "r"(addr));
}

static __device__ __forceinline__ void mma_f16(float* c, const uint32_t* a,
                                               uint32_t b0, uint32_t b1) {
    asm volatile(
        "mma.sync.aligned.m16n8k16.row.col.f32.f16.f16.f32 "
        "{%0,%1,%2,%3}, {%4,%5,%6,%7}, {%8,%9}, {%0,%1,%2,%3};"
        : "+f"(c[0]), "+f"(c[1]), "+f"(c[2]), "+f"(c[3])
        : "r"(a[0]), "r"(a[1]), "r"(a[2]), "r"(a[3]), "r"(b0), "r"(b1));
}

static __device__ __forceinline__ void cp_async16(uint32_t saddr, const void* gptr) {
    asm volatile("cp.async.cg.shared.global [%0], [%1], 16;"
                 :: "r"(saddr), "l"(gptr) : "memory");
}
#define CP_COMMIT() asm volatile("cp.async.commit_group;" ::: "memory")
#define CP_WAIT0()  asm volatile("cp.async.wait_group 0;" ::: "memory")

static __device__ __forceinline__ uint32_t pack_h(__half a, __half b) {
    __half2 t(a, b);
    return *reinterpret_cast<uint32_t*>(&t);
}

// Accurate fp32 tanh (Eigen-style rational, ~few-ulp in [-7.9, 7.9]).
static __device__ __forceinline__ float tanh_fast(float x) {
    float xc = fminf(fmaxf(x, -7.90531110763549805f), 7.90531110763549805f);
    float x2 = xc * xc;
    float p = fmaf(x2, -2.76076847742355e-16f, 2.00018790482477e-13f);
    p = fmaf(p, x2, -8.60467152213735e-11f);
    p = fmaf(p, x2, 5.12229709037114e-08f);
    p = fmaf(p, x2, 1.48572235717979e-05f);
    p = fmaf(p, x2, 6.37261928875436e-04f);
    p = fmaf(p, x2, 4.89352455891786e-03f);
    float q = fmaf(x2, 1.19825839466702e-06f, 1.18534705686654e-04f);
    q = fmaf(q, x2, 2.26843463243900e-03f);
    q = fmaf(q, x2, 4.89352518554385e-03f);
    return __fdividef(xc * p, q);
}

// =====================================================================
// Setup: convert Wq/Wk fp32 -> fp16 in global scratch (weights fp16-quantized;
// the activation side carries the hi+lo split, so the dropped term is A·Bl
// ~2^-11 relative on z — well under the 1e-3 gate).
// =====================================================================
__global__ void wsplit_kernel(const float* __restrict__ Wq, const float* __restrict__ Wk) {
    const int i = blockIdx.x * 256 + threadIdx.x;
    g_Wqh[i] = __float2half_rn(Wq[i]);
    g_Wkh[i] = __float2half_rn(Wk[i]);
}

// =====================================================================
// Scores via HMMA (mma.sync fp16, 2-pass activation split: Ah·Bh + Al·Bh),
// double-buffered software pipeline:
//   STS A(cur); wait B(cur); sync; prefetch A/B(next); MMA(cur)
// =====================================================================
__global__ __launch_bounds__(256, 2)
void scores_mma_kernel(const float* __restrict__ Q, const float* __restrict__ K,
                       const float* __restrict__ Wv) {
    extern __shared__ __align__(128) char dyn[];
    __shared__ float s_wv[HH];
    __shared__ float s_red[2][TILE_M];

    const int tid = threadIdx.x;
    const int lane = tid & 31;
    const int wid = tid >> 5;
    const int warp_m = wid & 3;      // 4 m-groups of 32 rows
    const int warp_n = wid >> 2;     // 2 n-groups of 64 cols
    const int m0 = blockIdx.x * TILE_M;

    s_wv[tid] = Wv[tid];

    const uint32_t base = smem_u32(dyn);
    // tile(buf, which): which: 0=Ah 1=Al 2=Bh
#define STILE(buf, w) (base + ((buf) * 3 + (w)) * TILE_BYTES)

    // per-lane ldmatrix byte offsets (within a tile)
    uint32_t aoff[2][2];
#pragma unroll
    for (int mi = 0; mi < 2; mi++)
#pragma unroll
        for (int ks = 0; ks < 2; ks++)
            aoff[mi][ks] = (uint32_t)((warp_m * 32 + mi * 16 + (lane & 15)) * (SA * 2)
                                      + (ks * 16 + ((lane >> 4) * 8)) * 2);
    uint32_t boff[4][2];
#pragma unroll
    for (int ntp = 0; ntp < 4; ntp++)
#pragma unroll
        for (int ks = 0; ks < 2; ks++)
            boff[ntp][ks] = (uint32_t)((warp_n * 64 + ntp * 16 + (lane & 7) + ((lane >> 4) << 3)) * (SA * 2)
                                       + ks * 32 + ((lane >> 3) & 1) * 16);

    // A-staging thread geometry
    const int ar = tid >> 3;         // row 0..31 (x4 j-steps cover 128)
    const int ac4 = tid & 7;         // float4 within 32-d chunk
    // B cp.async thread geometry
    const int br = tid >> 2;         // row 0..63 (x2 j-steps cover 128)
    const int bc8 = tid & 3;         // uint4 (8 fp16) within chunk

    float sp[4] = {0.f, 0.f, 0.f, 0.f};

#pragma unroll 1
    for (int hb = 0; hb < 2; hb++) {
        float c[2][8][4];
#pragma unroll
        for (int mi = 0; mi < 2; mi++)
#pragma unroll
            for (int nt = 0; nt < 8; nt++)
#pragma unroll
                for (int r = 0; r < 4; r++) c[mi][nt][r] = 0.f;

        uint32_t ah[8], al[8];   // staged converted A for "next" chunk

        // ---- prestage it=0 (src=Q, d0=0) ----
        {
#pragma unroll
            for (int j = 0; j < 4; j++) {
                const int r = ar + 32 * j;
                const float4 v = *reinterpret_cast<const float4*>(
                    Q + (size_t)(m0 + r) * DD + 0 + ac4 * 4);
                const __half hx = __float2half_rn(v.x);
                const __half hy = __float2half_rn(v.y);
                const __half hz = __float2half_rn(v.z);
                const __half hw = __float2half_rn(v.w);
                ah[2*j]   = pack_h(hx, hy);
                ah[2*j+1] = pack_h(hz, hw);
                al[2*j]   = pack_h(__float2half_rn(v.x - __half2float(hx)),
                                   __float2half_rn(v.y - __half2float(hy)));
                al[2*j+1] = pack_h(__float2half_rn(v.z - __half2float(hz)),
                                   __float2half_rn(v.w - __half2float(hw)));
            }
#pragma unroll
            for (int j = 0; j < 2; j++) {
                const int r = br + 64 * j;
                const size_t goff = (size_t)(hb * 128 + r) * DD + 0 + bc8 * 8;
                const uint32_t soff = (uint32_t)(r * SA + bc8 * 8) * 2;
                cp_async16(STILE(0, 2) + soff, g_Wqh + goff);
            }
            CP_COMMIT();
        }

#pragma unroll 1
        for (int it = 0; it < 16; it++) {
            const int buf = it & 1;

            // ---- STS staged A ----
#pragma unroll
            for (int j = 0; j < 4; j++) {
                const int r = ar + 32 * j;
                const uint32_t soff = (uint32_t)(r * SA + ac4 * 4) * 2;
                asm volatile("st.shared.v2.u32 [%0], {%1, %2};"
                             :: "r"(STILE(buf, 0) + soff), "r"(ah[2*j]), "r"(ah[2*j+1]));
                asm volatile("st.shared.v2.u32 [%0], {%1, %2};"
                             :: "r"(STILE(buf, 1) + soff), "r"(al[2*j]), "r"(al[2*j+1]));
            }
            CP_WAIT0();          // B(it) delivered
            __syncthreads();

            // ---- prefetch (it+1): LDG+convert A to regs, cp.async B ----
            if (it < 15) {
                const int nit = it + 1;
                const int nsrc = nit >> 3;
                const int nd0 = (nit & 7) * KC;
                const float* X = nsrc ? K : Q;
                const __half* WhG = nsrc ? g_Wkh : g_Wqh;
#pragma unroll
                for (int j = 0; j < 2; j++) {
                    const int r = br + 64 * j;
                    const size_t goff = (size_t)(hb * 128 + r) * DD + nd0 + bc8 * 8;
                    const uint32_t soff = (uint32_t)(r * SA + bc8 * 8) * 2;
                    cp_async16(STILE(buf ^ 1, 2) + soff, WhG + goff);
                }
                CP_COMMIT();
#pragma unroll
                for (int j = 0; j < 4; j++) {
                    const int r = ar + 32 * j;
                    const float4 v = *reinterpret_cast<const float4*>(
                        X + (size_t)(m0 + r) * DD + nd0 + ac4 * 4);
                    const __half hx = __float2half_rn(v.x);
                    const __half hy = __float2half_rn(v.y);
                    const __half hz = __float2half_rn(v.z);
                    const __half hw = __float2half_rn(v.w);
                    ah[2*j]   = pack_h(hx, hy);
                    ah[2*j+1] = pack_h(hz, hw);
                    al[2*j]   = pack_h(__float2half_rn(v.x - __half2float(hx)),
                                       __float2half_rn(v.y - __half2float(hy)));
                    al[2*j+1] = pack_h(__float2half_rn(v.z - __half2float(hz)),
                                       __float2half_rn(v.w - __half2float(hw)));
                }
            }

            // ---- 2 passes: Ah·Bh, Al·Bh ----
#pragma unroll
            for (int p = 0; p < 2; p++) {
                const uint32_t aBase = STILE(buf, p);
                const uint32_t bBase = STILE(buf, 2);
#pragma unroll
                for (int ks = 0; ks < 2; ks++) {
                    uint32_t a0[4], a1[4];
                    ldsm_x4(a0[0], a0[1], a0[2], a0[3], aBase + aoff[0][ks]);
                    ldsm_x4(a1[0], a1[1], a1[2], a1[3], aBase + aoff[1][ks]);
#pragma unroll
                    for (int ntp = 0; ntp < 4; ntp++) {
                        uint32_t b0, b1, b2, b3;
                        ldsm_x4(b0, b1, b2, b3, bBase + boff[ntp][ks]);
                        mma_f16(c[0][ntp * 2 + 0], a0, b0, b1);
                        mma_f16(c[0][ntp * 2 + 1], a0, b2, b3);
                        mma_f16(c[1][ntp * 2 + 0], a1, b0, b1);
                        mma_f16(c[1][ntp * 2 + 1], a1, b2, b3);
                    }
                }
            }
        }

        // ---- epilogue for this h-block: tanh + Wv dot into sp ----
#pragma unroll
        for (int mi = 0; mi < 2; mi++)
#pragma unroll
            for (int nt = 0; nt < 8; nt++) {
                const int col = hb * 128 + warp_n * 64 + nt * 8 + (lane & 3) * 2;
                const float w0 = s_wv[col], w1 = s_wv[col + 1];
                sp[mi * 2 + 0] = fmaf(w0, tanh_fast(c[mi][nt][0]),
                                 fmaf(w1, tanh_fast(c[mi][nt][1]), sp[mi * 2 + 0]));
                sp[mi * 2 + 1] = fmaf(w0, tanh_fast(c[mi][nt][2]),
                                 fmaf(w1, tanh_fast(c[mi][nt][3]), sp[mi * 2 + 1]));
            }
    }

    // ---- reduce: 4 lanes sharing a row -> butterfly; then across warp_n ----
#pragma unroll
    for (int i = 0; i < 4; i++) {
        sp[i] += __shfl_xor_sync(0xFFFFFFFFu, sp[i], 1);
        sp[i] += __shfl_xor_sync(0xFFFFFFFFu, sp[i], 2);
    }
    __syncthreads();
    if ((lane & 3) == 0) {
#pragma unroll
        for (int mi = 0; mi < 2; mi++)
#pragma unroll
            for (int half = 0; half < 2; half++) {
                const int row = warp_m * 32 + mi * 16 + half * 8 + (lane >> 2);
                s_red[warp_n][row] = sp[mi * 2 + half];
            }
    }
    __syncthreads();
    if (tid < TILE_M)
        g_scores[m0 + tid] = s_red[0][tid] + s_red[1][tid];
#undef STILE
}

// =====================================================================
// Kernel B: per-batch max / first-occurrence argmax / softmax denominator.
// =====================================================================
__global__ void stats_kernel(float* __restrict__ out, int out_size) {
    const int b = blockIdx.x;
    const int tid = threadIdx.x;
    const float* s = g_scores + (long)b * NN;

    float m = -INFINITY;
    int mi = 0;
    for (int n = tid; n < NN; n += 256) {
        const float v = s[n];
        if (v > m) { m = v; mi = n; }
    }
    __shared__ float sm[256];
    __shared__ int   si[256];
    sm[tid] = m; si[tid] = mi;
    __syncthreads();
    for (int o = 128; o > 0; o >>= 1) {
        if (tid < o) {
            const float v = sm[tid + o]; const int vi = si[tid + o];
            if (v > sm[tid] || (v == sm[tid] && vi < si[tid])) { sm[tid] = v; si[tid] = vi; }
        }
        __syncthreads();
    }
    const float mx = sm[0];
    const int amax = si[0];
    __syncthreads();

    float acc = 0.f;
    for (int n = tid; n < NN; n += 256) acc += expf(s[n] - mx);
    sm[tid] = acc;
    __syncthreads();
    for (int o = 128; o > 0; o >>= 1) {
        if (tid < o) sm[tid] += sm[tid + o];
        __syncthreads();
    }
    if (tid == 0) {
        g_bmax[b] = mx;
        g_bden[b] = sm[0];
        if (out_size >= BB * DD + BB) out[BB * DD + b] = (float)amax;
    }
}

// =====================================================================
// Kernel C: partial weighted sums (deterministic, no atomics)
// chunk = 128 rows; grid (NCHUNK=32, BB). float4 loads, 4 row-groups.
// =====================================================================
#define CROWS (NN / NCHUNK)   // 128
__global__ void weighted_kernel(const float* __restrict__ V) {
    const int chunk = blockIdx.x;
    const int b = blockIdx.y;
    const int tid = threadIdx.x;

    __shared__ float w[CROWS];
    __shared__ float part[4][DD];
    const float mx = g_bmax[b];
    const float inv = 1.0f / g_bden[b];
    const int n0 = chunk * CROWS;
    if (tid < CROWS)
        w[tid] = expf(g_scores[(long)b * NN + n0 + tid] - mx) * inv;
    __syncthreads();

    const int rg = tid >> 6;        // row-group 0..3
    const int c4 = tid & 63;        // float4 column
    const float4* Vp = reinterpret_cast<const float4*>(
        V + ((long)b * NN + n0) * DD) + c4;
    float4 acc = {0.f, 0.f, 0.f, 0.f};
#pragma unroll 8
    for (int n = rg; n < CROWS; n += 4) {
        const float4 v = Vp[(long)n * (DD / 4)];
        const float ww = w[n];
        acc.x = fmaf(ww, v.x, acc.x);
        acc.y = fmaf(ww, v.y, acc.y);
        acc.z = fmaf(ww, v.z, acc.z);
        acc.w = fmaf(ww, v.w, acc.w);
    }
    *reinterpret_cast<float4*>(&part[rg][c4 * 4]) = acc;
    __syncthreads();
    g_part[b][chunk][tid] = part[0][tid] + part[1][tid] + part[2][tid] + part[3][tid];
}

// =====================================================================
// Kernel D: reduce partials -> out[b, d]
// =====================================================================
__global__ void finalize_kernel(float* __restrict__ out) {
    const int b = blockIdx.x;
    const int tid = threadIdx.x;
    float acc = 0.f;
#pragma unroll
    for (int c = 0; c < NCHUNK; c++) acc += g_part[b][c][tid];
    out[b * DD + tid] = acc;
}

// =====================================================================
extern "C" void kernel_launch(void* const* d_in, const int* in_sizes, int n_in,
                              void* d_out, int out_size) {
    const float* Q  = (const float*)d_in[0];
    const float* K  = (const float*)d_in[1];
    const float* V  = (const float*)d_in[2];
    const float* Wq = (const float*)d_in[3];
    const float* Wk = (const float*)d_in[4];
    const float* Wv = (const float*)d_in[5];
    float* out = (float*)d_out;

    cudaFuncSetAttribute(scores_mma_kernel,
                         cudaFuncAttributeMaxDynamicSharedMemorySize, DYN_SMEM);

    wsplit_kernel<<<HH * DD / 256, 256>>>(Wq, Wk);
    scores_mma_kernel<<<NTILES, 256, DYN_SMEM>>>(Q, K, Wv);
    stats_kernel<<<BB, 256>>>(out, out_size);
    weighted_kernel<<<dim3(NCHUNK, BB), 256>>>(V);
    finalize_kernel<<<BB, DD>>>(out);
}

// round 9
// speedup vs baseline: 4.4053x; 1.3090x over previous
#include <cuda_runtime.h>
#include <cuda_fp16.h>
#include <cstdint>
#include <math.h>

// Shapes fixed by the reference: B=32, N=4096, D=256, H=256
#define BB 32
#define NN 4096
#define DD 256
#define HH 256
#define MTOT (BB * NN)          // 131072 rows
#define TILE_M 64               // rows per CTA
#define NTILES (MTOT / TILE_M)  // 2048
#define NCHUNK 64
#define KC 32                   // d-chunk
#define SA 40                   // padded smem row stride in fp16 elems (80 B)
#define A_BYTES (TILE_M * SA * 2)     // 5120
#define B_BYTES (HH * SA * 2)         // 20480
#define BUF_BYTES (A_BYTES + B_BYTES) // 25600
#define DYN_SMEM (2 * BUF_BYTES)      // 51200

// ---------------- device scratch (no allocation allowed) ----------------
__device__ float g_scores[MTOT];
__device__ float g_bmax[BB];
__device__ float g_bden[BB];
__device__ float g_part[BB][NCHUNK][DD];
__device__ __align__(16) __half g_Wqh[HH * DD];
__device__ __align__(16) __half g_Wkh[HH * DD];

// ---------------- helpers ----------------
static __device__ __forceinline__ uint32_t smem_u32(const void* p) {
    uint32_t a;
    asm("{ .reg .u64 t; cvta.to.shared.u64 t, %1; cvt.u32.u64 %0, t; }"
        : "=r"(a) : "l"(p));
    return a;
}

static __device__ __forceinline__ void ldsm_x4(uint32_t& r0, uint32_t& r1,
                                               uint32_t& r2, uint32_t& r3,
                                               uint32_t addr) {
    asm volatile("ldmatrix.sync.aligned.m8n8.x4.shared.b16 {%0,%1,%2,%3}, [%4];"
                 : "=r"(r0), "=r"(r1), "=r"(r2), "=r"(r3) : "r"(addr));
}

static __device__ __forceinline__ void mma_f16(float* c, const uint32_t* a,
                                               uint32_t b0, uint32_t b1) {
    asm volatile(
        "mma.sync.aligned.m16n8k16.row.col.f32.f16.f16.f32 "
        "{%0,%1,%2,%3}, {%4,%5,%6,%7}, {%8,%9}, {%0,%1,%2,%3};"
        : "+f"(c[0]), "+f"(c[1]), "+f"(c[2]), "+f"(c[3])
        : "r"(a[0]), "r"(a[1]), "r"(a[2]), "r"(a[3]), "r"(b0), "r"(b1));
}

static __device__ __forceinline__ void cp_async16(uint32_t saddr, const void* gptr) {
    asm volatile("cp.async.cg.shared.global [%0], [%1], 16;"
                 :: "r"(saddr), "l"(gptr) : "memory");
}
#define CP_COMMIT() asm volatile("cp.async.commit_group;" ::: "memory")
#define CP_WAIT0()  asm volatile("cp.async.wait_group 0;" ::: "memory")

static __device__ __forceinline__ uint32_t pack_h(__half a, __half b) {
    __half2 t(a, b);
    return *reinterpret_cast<uint32_t*>(&t);
}

// Accurate fp32 tanh (Eigen-style rational, ~few-ulp in [-7.9, 7.9]).
static __device__ __forceinline__ float tanh_fast(float x) {
    float xc = fminf(fmaxf(x, -7.90531110763549805f), 7.90531110763549805f);
    float x2 = xc * xc;
    float p = fmaf(x2, -2.76076847742355e-16f, 2.00018790482477e-13f);
    p = fmaf(p, x2, -8.60467152213735e-11f);
    p = fmaf(p, x2, 5.12229709037114e-08f);
    p = fmaf(p, x2, 1.48572235717979e-05f);
    p = fmaf(p, x2, 6.37261928875436e-04f);
    p = fmaf(p, x2, 4.89352455891786e-03f);
    float q = fmaf(x2, 1.19825839466702e-06f, 1.18534705686654e-04f);
    q = fmaf(q, x2, 2.26843463243900e-03f);
    q = fmaf(q, x2, 4.89352518554385e-03f);
    return __fdividef(xc * p, q);
}

// =====================================================================
// Setup: convert Wq/Wk fp32 -> fp16 in global scratch.
// =====================================================================
__global__ void wsplit_kernel(const float* __restrict__ Wq, const float* __restrict__ Wk) {
    const int i = blockIdx.x * 256 + threadIdx.x;
    g_Wqh[i] = __float2half_rn(Wq[i]);
    g_Wkh[i] = __float2half_rn(Wk[i]);
}

// =====================================================================
// Scores via HMMA, single fp16 pass. CTA tile: 64 rows x 256 h (full H).
// 8 warps: warp_m in {0,1} (32-row halves), warp_n in {0..3} (64-col groups).
// 16 iterations: it<8 -> Q x Wq chunks, it>=8 -> K x Wk chunks.
// Double-buffered: STS A(cur); wait B(cur); sync; prefetch(next); MMA(cur).
// =====================================================================
__global__ __launch_bounds__(256, 2)
void scores_mma_kernel(const float* __restrict__ Q, const float* __restrict__ K,
                       const float* __restrict__ Wv) {
    extern __shared__ __align__(128) char dyn[];
    __shared__ float s_wv[HH];
    __shared__ float s_red[4][TILE_M];

    const int tid = threadIdx.x;
    const int lane = tid & 31;
    const int wid = tid >> 5;
    const int warp_m = wid & 1;      // 2 m-groups of 32 rows
    const int warp_n = wid >> 1;     // 4 n-groups of 64 cols
    const int m0 = blockIdx.x * TILE_M;

    s_wv[tid] = Wv[tid];

    const uint32_t base = smem_u32(dyn);
#define SA_TILE(buf) (base + (buf) * BUF_BYTES)
#define SB_TILE(buf) (base + (buf) * BUF_BYTES + A_BYTES)

    // per-lane ldmatrix byte offsets (within a tile)
    uint32_t aoff[2][2];   // [mi][ks]
#pragma unroll
    for (int mi = 0; mi < 2; mi++)
#pragma unroll
        for (int ks = 0; ks < 2; ks++)
            aoff[mi][ks] = (uint32_t)((warp_m * 32 + mi * 16 + (lane & 15)) * (SA * 2)
                                      + (ks * 16 + ((lane >> 4) * 8)) * 2);
    uint32_t boff[4][2];   // [ntp][ks]
#pragma unroll
    for (int ntp = 0; ntp < 4; ntp++)
#pragma unroll
        for (int ks = 0; ks < 2; ks++)
            boff[ntp][ks] = (uint32_t)((warp_n * 64 + ntp * 16 + (lane & 7) + ((lane >> 4) << 3)) * (SA * 2)
                                       + ks * 32 + ((lane >> 3) & 1) * 16);

    // A-staging geometry: 64 rows x 8 float4 = 512; 2 per thread
    const int ar = tid >> 3;         // row 0..31 (j adds 32)
    const int ac4 = tid & 7;
    // B cp.async geometry: 256 rows x 4 uint4 = 1024; 4 per thread
    const int br = tid >> 2;         // row 0..63 (j adds 64)
    const int bc8 = tid & 3;

    float c[2][8][4];
#pragma unroll
    for (int mi = 0; mi < 2; mi++)
#pragma unroll
        for (int nt = 0; nt < 8; nt++)
#pragma unroll
            for (int r = 0; r < 4; r++) c[mi][nt][r] = 0.f;

    uint32_t ah[4];   // staged converted A for "next" chunk (2 float4 -> 4 h2)

    // ---- prestage it=0 (src=Q, d0=0) ----
    {
#pragma unroll
        for (int j = 0; j < 2; j++) {
            const int r = ar + 32 * j;
            const float4 v = *reinterpret_cast<const float4*>(
                Q + (size_t)(m0 + r) * DD + 0 + ac4 * 4);
            ah[2*j]   = pack_h(__float2half_rn(v.x), __float2half_rn(v.y));
            ah[2*j+1] = pack_h(__float2half_rn(v.z), __float2half_rn(v.w));
        }
#pragma unroll
        for (int j = 0; j < 4; j++) {
            const int r = br + 64 * j;
            const size_t goff = (size_t)r * DD + 0 + bc8 * 8;
            const uint32_t soff = (uint32_t)(r * SA + bc8 * 8) * 2;
            cp_async16(SB_TILE(0) + soff, g_Wqh + goff);
        }
        CP_COMMIT();
    }

#pragma unroll 1
    for (int it = 0; it < 16; it++) {
        const int buf = it & 1;

        // ---- STS staged A ----
#pragma unroll
        for (int j = 0; j < 2; j++) {
            const int r = ar + 32 * j;
            const uint32_t soff = (uint32_t)(r * SA + ac4 * 4) * 2;
            asm volatile("st.shared.v2.u32 [%0], {%1, %2};"
                         :: "r"(SA_TILE(buf) + soff), "r"(ah[2*j]), "r"(ah[2*j+1]));
        }
        CP_WAIT0();          // B(it) delivered
        __syncthreads();

        // ---- prefetch (it+1): LDG+convert A to regs, cp.async B ----
        if (it < 15) {
            const int nit = it + 1;
            const int nsrc = nit >> 3;
            const int nd0 = (nit & 7) * KC;
            const float* X = nsrc ? K : Q;
            const __half* WhG = nsrc ? g_Wkh : g_Wqh;
#pragma unroll
            for (int j = 0; j < 4; j++) {
                const int r = br + 64 * j;
                const size_t goff = (size_t)r * DD + nd0 + bc8 * 8;
                const uint32_t soff = (uint32_t)(r * SA + bc8 * 8) * 2;
                cp_async16(SB_TILE(buf ^ 1) + soff, WhG + goff);
            }
            CP_COMMIT();
#pragma unroll
            for (int j = 0; j < 2; j++) {
                const int r = ar + 32 * j;
                const float4 v = *reinterpret_cast<const float4*>(
                    X + (size_t)(m0 + r) * DD + nd0 + ac4 * 4);
                ah[2*j]   = pack_h(__float2half_rn(v.x), __float2half_rn(v.y));
                ah[2*j+1] = pack_h(__float2half_rn(v.z), __float2half_rn(v.w));
            }
        }

        // ---- MMA (single fp16 pass) ----
#pragma unroll
        for (int ks = 0; ks < 2; ks++) {
            uint32_t a0[4], a1[4];
            ldsm_x4(a0[0], a0[1], a0[2], a0[3], SA_TILE(buf) + aoff[0][ks]);
            ldsm_x4(a1[0], a1[1], a1[2], a1[3], SA_TILE(buf) + aoff[1][ks]);
#pragma unroll
            for (int ntp = 0; ntp < 4; ntp++) {
                uint32_t b0, b1, b2, b3;
                ldsm_x4(b0, b1, b2, b3, SB_TILE(buf) + boff[ntp][ks]);
                mma_f16(c[0][ntp * 2 + 0], a0, b0, b1);
                mma_f16(c[0][ntp * 2 + 1], a0, b2, b3);
                mma_f16(c[1][ntp * 2 + 0], a1, b0, b1);
                mma_f16(c[1][ntp * 2 + 1], a1, b2, b3);
            }
        }
    }

    // ---- epilogue: tanh + Wv dot ----
    float sp[4] = {0.f, 0.f, 0.f, 0.f};
#pragma unroll
    for (int mi = 0; mi < 2; mi++)
#pragma unroll
        for (int nt = 0; nt < 8; nt++) {
            const int col = warp_n * 64 + nt * 8 + (lane & 3) * 2;
            const float w0 = s_wv[col], w1 = s_wv[col + 1];
            sp[mi * 2 + 0] = fmaf(w0, tanh_fast(c[mi][nt][0]),
                             fmaf(w1, tanh_fast(c[mi][nt][1]), sp[mi * 2 + 0]));
            sp[mi * 2 + 1] = fmaf(w0, tanh_fast(c[mi][nt][2]),
                             fmaf(w1, tanh_fast(c[mi][nt][3]), sp[mi * 2 + 1]));
        }

    // reduce 4 col-lanes -> row totals
#pragma unroll
    for (int i = 0; i < 4; i++) {
        sp[i] += __shfl_xor_sync(0xFFFFFFFFu, sp[i], 1);
        sp[i] += __shfl_xor_sync(0xFFFFFFFFu, sp[i], 2);
    }
    __syncthreads();
    if ((lane & 3) == 0) {
#pragma unroll
        for (int mi = 0; mi < 2; mi++)
#pragma unroll
            for (int half = 0; half < 2; half++) {
                const int row = warp_m * 32 + mi * 16 + half * 8 + (lane >> 2);
                s_red[warp_n][row] = sp[mi * 2 + half];
            }
    }
    __syncthreads();
    if (tid < TILE_M)
        g_scores[m0 + tid] = (s_red[0][tid] + s_red[1][tid])
                           + (s_red[2][tid] + s_red[3][tid]);
#undef SA_TILE
#undef SB_TILE
}

// =====================================================================
// Kernel B: per-batch max / first-occurrence argmax / softmax denominator.
// =====================================================================
__global__ __launch_bounds__(1024)
void stats_kernel(float* __restrict__ out, int out_size) {
    const int b = blockIdx.x;
    const int tid = threadIdx.x;
    const float* s = g_scores + (long)b * NN;

    float m = -INFINITY;
    int mi = 0;
    for (int n = tid; n < NN; n += 1024) {
        const float v = s[n];
        if (v > m) { m = v; mi = n; }
    }
    __shared__ float sm[1024];
    __shared__ int   si[1024];
    sm[tid] = m; si[tid] = mi;
    __syncthreads();
    for (int o = 512; o > 0; o >>= 1) {
        if (tid < o) {
            const float v = sm[tid + o]; const int vi = si[tid + o];
            if (v > sm[tid] || (v == sm[tid] && vi < si[tid])) { sm[tid] = v; si[tid] = vi; }
        }
        __syncthreads();
    }
    const float mx = sm[0];
    const int amax = si[0];
    __syncthreads();

    float acc = 0.f;
    for (int n = tid; n < NN; n += 1024) acc += expf(s[n] - mx);
    sm[tid] = acc;
    __syncthreads();
    for (int o = 512; o > 0; o >>= 1) {
        if (tid < o) sm[tid] += sm[tid + o];
        __syncthreads();
    }
    if (tid == 0) {
        g_bmax[b] = mx;
        g_bden[b] = sm[0];
        if (out_size >= BB * DD + BB) out[BB * DD + b] = (float)amax;
    }
}

// =====================================================================
// Kernel C: partial weighted sums (deterministic, no atomics)
// chunk = 64 rows; grid (NCHUNK=64, BB). float4 loads, 4 row-groups.
// =====================================================================
#define CROWS (NN / NCHUNK)   // 64
__global__ void weighted_kernel(const float* __restrict__ V) {
    const int chunk = blockIdx.x;
    const int b = blockIdx.y;
    const int tid = threadIdx.x;

    __shared__ float w[CROWS];
    __shared__ float part[4][DD];
    const float mx = g_bmax[b];
    const float inv = 1.0f / g_bden[b];
    const int n0 = chunk * CROWS;
    if (tid < CROWS)
        w[tid] = expf(g_scores[(long)b * NN + n0 + tid] - mx) * inv;
    __syncthreads();

    const int rg = tid >> 6;        // row-group 0..3
    const int c4 = tid & 63;        // float4 column
    const float4* Vp = reinterpret_cast<const float4*>(
        V + ((long)b * NN + n0) * DD) + c4;
    float4 acc = {0.f, 0.f, 0.f, 0.f};
#pragma unroll 8
    for (int n = rg; n < CROWS; n += 4) {
        const float4 v = Vp[(long)n * (DD / 4)];
        const float ww = w[n];
        acc.x = fmaf(ww, v.x, acc.x);
        acc.y = fmaf(ww, v.y, acc.y);
        acc.z = fmaf(ww, v.z, acc.z);
        acc.w = fmaf(ww, v.w, acc.w);
    }
    *reinterpret_cast<float4*>(&part[rg][c4 * 4]) = acc;
    __syncthreads();
    g_part[b][chunk][tid] = part[0][tid] + part[1][tid] + part[2][tid] + part[3][tid];
}

// =====================================================================
// Kernel D: reduce partials -> out[b, d]
// =====================================================================
__global__ void finalize_kernel(float* __restrict__ out) {
    const int b = blockIdx.x;
    const int tid = threadIdx.x;
    float acc = 0.f;
#pragma unroll
    for (int c = 0; c < NCHUNK; c++) acc += g_part[b][c][tid];
    out[b * DD + tid] = acc;
}

// =====================================================================
extern "C" void kernel_launch(void* const* d_in, const int* in_sizes, int n_in,
                              void* d_out, int out_size) {
    const float* Q  = (const float*)d_in[0];
    const float* K  = (const float*)d_in[1];
    const float* V  = (const float*)d_in[2];
    const float* Wq = (const float*)d_in[3];
    const float* Wk = (const float*)d_in[4];
    const float* Wv = (const float*)d_in[5];
    float* out = (float*)d_out;

    cudaFuncSetAttribute(scores_mma_kernel,
                         cudaFuncAttributeMaxDynamicSharedMemorySize, DYN_SMEM);

    wsplit_kernel<<<HH * DD / 256, 256>>>(Wq, Wk);
    scores_mma_kernel<<<NTILES, 256, DYN_SMEM>>>(Q, K, Wv);
    stats_kernel<<<BB, 1024>>>(out, out_size);
    weighted_kernel<<<dim3(NCHUNK, BB), 256>>>(V);
    finalize_kernel<<<BB, DD>>>(out);
}